// round 10
// baseline (speedup 1.0000x reference)
#include <cuda_runtime.h>
#include <cstdint>

#define F_     128
#define NE_    132
#define MT_    128
#define NTHR   512
#define ASTR_B 272u          // A row stride bytes (136 f16)
#define BSTR_B 272u
#define CSTR_W 20
#define RES_KS 3             // B fragments for ks 0..RES_KS-1 live in registers

#define OFF_A0   0u          // [128][272B] : 34816
#define OFF_A1   34816u
#define ABUF     34816u
#define OFF_BT   69632u      // [136][272B] : 36992
#define OFF_CHI0 106624u     // [128][20] f32 : 10240
#define OFF_CHI1 116864u
#define OFF_BIAS 127104u     // 136 f32
#define SMEM_REQ 127648u

__device__ __forceinline__ uint32_t s2u(const void* p) {
    uint32_t a;
    asm("{ .reg .u64 t; cvta.to.shared.u64 t, %1; cvt.u32.u64 %0, t; }"
        : "=r"(a) : "l"(p));
    return a;
}
__device__ __forceinline__ uint32_t packh(float v0, float v1) {
    uint32_t r;
    asm("cvt.rn.f16x2.f32 %0, %1, %2;" : "=r"(r) : "f"(v1), "f"(v0));
    return r;
}
__device__ __forceinline__ void mma16(float* c, const uint32_t* a,
                                      uint32_t b0, uint32_t b1) {
    asm volatile(
        "mma.sync.aligned.m16n8k16.row.col.f32.f16.f16.f32 "
        "{%0,%1,%2,%3}, {%4,%5,%6,%7}, {%8,%9}, {%0,%1,%2,%3};"
        : "+f"(c[0]), "+f"(c[1]), "+f"(c[2]), "+f"(c[3])
        : "r"(a[0]), "r"(a[1]), "r"(a[2]), "r"(a[3]), "r"(b0), "r"(b1));
}
__device__ __forceinline__ void mma8(float* c, uint32_t a0, uint32_t a1,
                                     uint32_t b0) {
    asm volatile(
        "mma.sync.aligned.m16n8k8.row.col.f32.f16.f16.f32 "
        "{%0,%1,%2,%3}, {%4,%5}, {%6}, {%0,%1,%2,%3};"
        : "+f"(c[0]), "+f"(c[1]), "+f"(c[2]), "+f"(c[3])
        : "r"(a0), "r"(a1), "r"(b0));
}
__device__ __forceinline__ void ldm4(uint32_t* r, uint32_t a) {
    asm volatile("ldmatrix.sync.aligned.m8n8.x4.shared.b16 {%0,%1,%2,%3}, [%4];"
                 : "=r"(r[0]), "=r"(r[1]), "=r"(r[2]), "=r"(r[3]) : "r"(a));
}
__device__ __forceinline__ void ldm2(uint32_t* r, uint32_t a) {
    asm volatile("ldmatrix.sync.aligned.m8n8.x2.shared.b16 {%0,%1}, [%2];"
                 : "=r"(r[0]), "=r"(r[1]) : "r"(a));
}
__device__ __forceinline__ void ldm1(uint32_t* r, uint32_t a) {
    asm volatile("ldmatrix.sync.aligned.m8n8.x1.shared.b16 {%0}, [%1];"
                 : "=r"(r[0]) : "r"(a));
}

// fetch one 32-row chunk of x (2 float4 = 8 regs)
__device__ __forceinline__ void fetch_xc(const float* __restrict__ x,
                                         float4* xr, int m0, int rv,
                                         int tid, int c) {
#pragma unroll
    for (int j = 0; j < 2; j++) {
        int e = tid + j * NTHR;
        int row = c * 32 + (e >> 5), c4 = e & 31;
        xr[j] = make_float4(0.f, 0.f, 0.f, 0.f);
        if (row < rv)
            xr[j] = *(const float4*)(x + (size_t)(m0 + row) * F_ + c4 * 4);
    }
}
__device__ __forceinline__ void sts_xc(char* __restrict__ sm, uint32_t aoff,
                                       const float4* xr, int tid, int c) {
    char* ab = sm + aoff;
#pragma unroll
    for (int j = 0; j < 2; j++) {
        int e = tid + j * NTHR;
        int row = c * 32 + (e >> 5), c4 = e & 31;
        uint32_t h0 = packh(xr[j].x, xr[j].y);
        uint32_t h1 = packh(xr[j].z, xr[j].w);
        *(uint2*)(ab + row * ASTR_B + c4 * 8) = make_uint2(h0, h1);
    }
}
__device__ __forceinline__ void fetch_chi(const float* __restrict__ chi,
                                          float4& cv, int m0, int rv, int tid) {
    int rowc = tid >> 2, seg = tid & 3;
    cv = make_float4(0.f, 0.f, 0.f, 0.f);
    if (rowc < rv)
        cv = *(const float4*)(chi + (size_t)(m0 + rowc) * 16 + seg * 4);
}
// chi stage + d_chi into A tail (kpairs 64..67)
__device__ __forceinline__ void sts_chi(char* __restrict__ sm, uint32_t aoff,
                                        float* __restrict__ csm,
                                        float4 cv, int tid) {
    char* ab = sm + aoff;
    int rowc = tid >> 2, seg = tid & 3;
    *(float4*)&csm[rowc * CSTR_W + seg * 4] = cv;
    float xx = cv.x * cv.x, yy = cv.y * cv.y, zz = cv.z * cv.z, ww = cv.w * cv.w;
    float av, bv;
    if (seg == 0)      { av = xx;                bv = yy + zz + ww; }
    else if (seg == 1) { av = xx + yy + zz + ww; bv = 0.f; }
    else if (seg == 2) { av = xx;                bv = yy + zz + ww; }
    else               { av = 0.f;               bv = xx + yy + zz + ww; }
    float a1v = __shfl_xor_sync(0xFFFFFFFFu, av, 1);
    float a2v = __shfl_xor_sync(0xFFFFFFFFu, av, 2);
    float b2v = __shfl_xor_sync(0xFFFFFFFFu, bv, 2);
    float b3v = __shfl_xor_sync(0xFFFFFFFFu, bv, 3);
    if (seg == 0) {
        uint32_t h0 = packh(av, bv);
        uint32_t h1 = packh(a1v + a2v, b2v + b3v);
        *(uint4*)(ab + rowc * ASTR_B + 256) = make_uint4(h0, h1, 0u, 0u);
    }
}

__global__ __launch_bounds__(NTHR, 1)
void ib_mma_kernel(const float* __restrict__ x, const float* __restrict__ chi,
                   const float* __restrict__ W, const float* __restrict__ b,
                   float* __restrict__ a1, float* __restrict__ chiout, int n)
{
    extern __shared__ char sm[];
    const uint32_t smb = s2u(sm);
    float* csm0 = (float*)(sm + OFF_CHI0);
    float* csm1 = (float*)(sm + OFF_CHI1);
    float* bias = (float*)(sm + OFF_BIAS);

    const int tid  = threadIdx.x;
    const int wid  = tid >> 5;
    const int lane = tid & 31;
    const int g    = lane >> 2;
    const int t4   = lane & 3;
    const int band = wid & 3;          // 32-row band
    const int q    = wid >> 2;         // N quarter
    const bool q3  = (q == 3);
    const int m    = lane >> 3;
    const int rin  = lane & 7;

    // lane-constant ldmatrix addresses (A relative to buffer 0)
    const uint32_t aA0 = smb + OFF_A0
        + (uint32_t)(band * 32 + (m & 1) * 8 + rin) * ASTR_B + (uint32_t)(m >> 1) * 16u;
    const uint32_t aA1 = aA0 + 16u * ASTR_B;
    const uint32_t aAt = smb + OFF_A0
        + (uint32_t)(band * 32 + (m >> 1) * 16 + (m & 1) * 8 + rin) * ASTR_B + 256u;
    const uint32_t aB0 = smb + OFF_BT
        + (uint32_t)(q * 32 + (m >> 1) * 8 + rin) * BSTR_B + (uint32_t)(m & 1) * 16u;
    const uint32_t aB1 = aB0 + 16u * BSTR_B;
    const uint32_t aB4 = smb + OFF_BT
        + (uint32_t)(q * 32 + 32 + rin) * BSTR_B + (uint32_t)(m & 1) * 16u;
    const uint32_t aBt = smb + OFF_BT
        + (uint32_t)(q * 32 + m * 8 + rin) * BSTR_B + 256u;
    const uint32_t aBt4 = smb + OFF_BT
        + (uint32_t)(q * 32 + 32 + rin) * BSTR_B + 256u;

    const int ntiles = (n + MT_ - 1) / MT_;
    int t = blockIdx.x;

    float4 xr[2];
    float4 cv;

    // ---- tile0 prologue: stage into buffer 0 ----
    {
        int m0p = t * MT_;
        int rvp = (n - m0p < MT_) ? (n - m0p) : MT_;
        fetch_xc(x, xr, m0p, rvp, tid, 0);
        // one-time: W -> Bt (f16 [n][k]), bias
        for (int e = tid; e < 136 * 68; e += NTHR) {
            int col = e / 68, kp = e - col * 68;
            int k0 = 2 * kp, k1 = k0 + 1;
            float w0 = (k0 < NE_ && col < NE_) ? W[k0 * NE_ + col] : 0.f;
            float w1 = (k1 < NE_ && col < NE_) ? W[k1 * NE_ + col] : 0.f;
            *(uint32_t*)(sm + OFF_BT + col * BSTR_B + kp * 4) = packh(w0, w1);
        }
        if (tid < 136) bias[tid] = (tid < NE_) ? b[tid] : 0.f;
        sts_xc(sm, OFF_A0, xr, tid, 0);
#pragma unroll
        for (int c = 1; c < 4; c++) {
            fetch_xc(x, xr, m0p, rvp, tid, c);
            sts_xc(sm, OFF_A0, xr, tid, c);
        }
        fetch_chi(chi, cv, m0p, rvp, tid);
        sts_chi(sm, OFF_A0, csm0, cv, tid);
    }
    __syncthreads();

    // ---- resident B fragments: ks 0..RES_KS-1 + k8 tail ----
    uint32_t Breg[RES_KS][10];
    uint32_t TBreg[5];
#pragma unroll
    for (int ks = 0; ks < RES_KS; ks++) {
        ldm4(&Breg[ks][0], aB0 + ks * 32);
        ldm4(&Breg[ks][4], aB1 + ks * 32);
        if (q3) ldm2(&Breg[ks][8], aB4 + ks * 32);
    }
    ldm4(TBreg, aBt);
    if (q3) ldm1(&TBreg[4], aBt4);

    // ---- persistent loop (one sync per tile) ----
    for (int i = 0; t < ntiles; i++, t += gridDim.x) {
        const int buf = i & 1;
        const uint32_t abuf = buf ? ABUF : 0u;
        const uint32_t nbuf = buf ? 0u : ABUF;
        float* csm  = buf ? csm1 : csm0;
        float* csmn = buf ? csm0 : csm1;
        const int m0 = t * MT_;
        const int rv = (n - m0 < MT_) ? (n - m0) : MT_;
        const int tn = t + gridDim.x;
        const bool more = (tn < ntiles);
        const int m0n = tn * MT_;
        const int rvn = more ? ((n - m0n < MT_) ? (n - m0n) : MT_) : 0;

        const uint32_t bA0 = aA0 + abuf;
        const uint32_t bA1 = aA1 + abuf;
        const uint32_t bAt = aAt + abuf;

        if (more) fetch_xc(x, xr, m0n, rvn, tid, 0);

        float acc[2][5][4];
#pragma unroll
        for (int mt = 0; mt < 2; mt++)
#pragma unroll
            for (int nt = 0; nt < 4; nt++) {
                int col = q * 32 + nt * 8 + t4 * 2;
                float b0 = bias[col], b1 = bias[col + 1];
                acc[mt][nt][0] = b0; acc[mt][nt][1] = b1;
                acc[mt][nt][2] = b0; acc[mt][nt][3] = b1;
            }
        if (q3) {
            float b0 = bias[128 + t4 * 2], b1 = bias[129 + t4 * 2];
#pragma unroll
            for (int mt = 0; mt < 2; mt++) {
                acc[mt][4][0] = b0; acc[mt][4][1] = b1;
                acc[mt][4][2] = b0; acc[mt][4][3] = b1;
            }
        }

        auto kstep = [&](int ks, const uint32_t* B) {
            uint32_t A0[4], A1[4];
            ldm4(A0, bA0 + ks * 32);
            ldm4(A1, bA1 + ks * 32);
            mma16(acc[0][0], A0, B[0], B[1]);
            mma16(acc[1][0], A1, B[0], B[1]);
            mma16(acc[0][1], A0, B[2], B[3]);
            mma16(acc[1][1], A1, B[2], B[3]);
            mma16(acc[0][2], A0, B[4], B[5]);
            mma16(acc[1][2], A1, B[4], B[5]);
            mma16(acc[0][3], A0, B[6], B[7]);
            mma16(acc[1][3], A1, B[6], B[7]);
            if (q3) {
                mma16(acc[0][4], A0, B[8], B[9]);
                mma16(acc[1][4], A1, B[8], B[9]);
            }
        };

        // ks 0..2: resident B, interleaved with chunked prefetch/STS
        kstep(0, Breg[0]);
        if (more) { sts_xc(sm, nbuf, xr, tid, 0); fetch_xc(x, xr, m0n, rvn, tid, 1); }
        kstep(1, Breg[1]);
        if (more) { sts_xc(sm, nbuf, xr, tid, 1); fetch_xc(x, xr, m0n, rvn, tid, 2); }
        kstep(2, Breg[2]);
        if (more) { sts_xc(sm, nbuf, xr, tid, 2); fetch_xc(x, xr, m0n, rvn, tid, 3); }

        // ks 3: smem B, then last chunk + chi prefetch
        {
            uint32_t Bs[10];
            ldm4(&Bs[0], aB0 + 3 * 32);
            ldm4(&Bs[4], aB1 + 3 * 32);
            if (q3) ldm2(&Bs[8], aB4 + 3 * 32);
            kstep(3, Bs);
        }
        if (more) { sts_xc(sm, nbuf, xr, tid, 3); fetch_chi(chi, cv, m0n, rvn, tid); }

        // ks 4..7: smem B
#pragma unroll
        for (int ks = 4; ks < 8; ks++) {
            uint32_t Bs[10];
            ldm4(&Bs[0], aB0 + ks * 32);
            ldm4(&Bs[4], aB1 + ks * 32);
            if (q3) ldm2(&Bs[8], aB4 + ks * 32);
            kstep(ks, Bs);
        }

        // tail k8 (d_chi k-rows 128..135), B resident
        {
            uint32_t TA[4];
            ldm4(TA, bAt);
#pragma unroll
            for (int nt = 0; nt < 4; nt++) {
                mma8(acc[0][nt], TA[0], TA[1], TBreg[nt]);
                mma8(acc[1][nt], TA[2], TA[3], TBreg[nt]);
            }
            if (q3) {
                mma8(acc[0][4], TA[0], TA[1], TBreg[4]);
                mma8(acc[1][4], TA[2], TA[3], TBreg[4]);
            }
        }

        // epilogue: a1
        {
            float* ab = a1 + (size_t)m0 * F_;
#pragma unroll
            for (int mt = 0; mt < 2; mt++) {
                int r0 = band * 32 + mt * 16 + g;
                int r1 = r0 + 8;
                bool v0 = (r0 < rv), v1 = (r1 < rv);
#pragma unroll
                for (int nt = 0; nt < 4; nt++) {
                    int col = q * 32 + nt * 8 + t4 * 2;
                    if (v0) *(float2*)&ab[(size_t)r0 * F_ + col] =
                                make_float2(acc[mt][nt][0], acc[mt][nt][1]);
                    if (v1) *(float2*)&ab[(size_t)r1 * F_ + col] =
                                make_float2(acc[mt][nt][2], acc[mt][nt][3]);
                }
            }
        }
        // chi_out from cols 128..131
        if (q3) {
#pragma unroll
            for (int mt = 0; mt < 2; mt++) {
                float c0 = acc[mt][4][0], c1 = acc[mt][4][1];
                float c2 = acc[mt][4][2], c3 = acc[mt][4][3];
                float o0 = __shfl_xor_sync(0xFFFFFFFFu, c0, 1);
                float o2 = __shfl_xor_sync(0xFFFFFFFFu, c2, 1);
                int rr0 = band * 32 + mt * 16 + g;
                int rr[2] = {rr0, rr0 + 8};
                if (t4 == 0) {
                    float b0r[2] = {c0, c2}, b1r[2] = {c1, c3}, b2r[2] = {o0, o2};
#pragma unroll
                    for (int h = 0; h < 2; h++) {
                        if (rr[h] < rv) {
                            const float* cr = &csm[rr[h] * CSTR_W];
                            float4 ca = *(const float4*)&cr[0];
                            float4 cb = *(const float4*)&cr[4];
                            float4 u, w;
                            u.x = b0r[h] * ca.x; u.y = b1r[h] * ca.y;
                            u.z = b1r[h] * ca.z; u.w = b1r[h] * ca.w;
                            w.x = b2r[h] * cb.x; w.y = b2r[h] * cb.y;
                            w.z = b2r[h] * cb.z; w.w = b2r[h] * cb.w;
                            float* op = &chiout[(size_t)(m0 + rr[h]) * 16];
                            *(float4*)&op[0] = u;
                            *(float4*)&op[4] = w;
                        }
                    }
                } else if (t4 == 1) {
                    float b2r[2] = {c0, c2}, b3r[2] = {c1, c3};
#pragma unroll
                    for (int h = 0; h < 2; h++) {
                        if (rr[h] < rv) {
                            const float* cr = &csm[rr[h] * CSTR_W];
                            float4 ca = *(const float4*)&cr[8];
                            float4 cb = *(const float4*)&cr[12];
                            float4 u, w;
                            u.x = b2r[h] * ca.x; u.y = b3r[h] * ca.y;
                            u.z = b3r[h] * ca.z; u.w = b3r[h] * ca.w;
                            w.x = b3r[h] * cb.x; w.y = b3r[h] * cb.y;
                            w.z = b3r[h] * cb.z; w.w = b3r[h] * cb.w;
                            float* op = &chiout[(size_t)(m0 + rr[h]) * 16];
                            *(float4*)&op[8]  = u;
                            *(float4*)&op[12] = w;
                        }
                    }
                }
            }
        }

        if (more) sts_chi(sm, nbuf, csmn, cv, tid);
        __syncthreads();
    }
}

extern "C" void kernel_launch(void* const* d_in, const int* in_sizes, int n_in,
                              void* d_out, int out_size) {
    const float* x   = (const float*)d_in[0];
    const float* chi = (const float*)d_in[1];
    // d_in[2] = point_mask (all ones; unused by the math)
    const float* W   = (const float*)d_in[3];
    const float* b   = (const float*)d_in[4];

    const int n = in_sizes[0] / F_;
    float* out    = (float*)d_out;
    float* a1     = out;
    float* chiout = out + (size_t)n * F_;

    cudaFuncSetAttribute(ib_mma_kernel,
                         cudaFuncAttributeMaxDynamicSharedMemorySize, SMEM_REQ);
    int ntiles = (n + MT_ - 1) / MT_;
    int grid = ntiles < 152 ? ntiles : 152;
    ib_mma_kernel<<<grid, NTHR, SMEM_REQ>>>(x, chi, W, b, a1, chiout, n);
}

// round 11
// speedup vs baseline: 1.4474x; 1.4474x over previous
#include <cuda_runtime.h>
#include <cstdint>

#define F_     128
#define NE_    132
#define MT_    128
#define NTHR   512
#define ASTR_B 272u          // A row stride bytes (136 f16)
#define BSTR_B 272u
#define CSTR_W 20

#define OFF_A    0u          // [128][272B] : 34816
#define OFF_BT   34816u      // [136][272B] : 36992
#define OFF_CHI  71808u      // [128][20] f32 : 10240
#define OFF_BIAS 82048u      // 136 f32 : 544
#define SMEM_REQ 82592u

__device__ __forceinline__ uint32_t s2u(const void* p) {
    uint32_t a;
    asm("{ .reg .u64 t; cvta.to.shared.u64 t, %1; cvt.u32.u64 %0, t; }"
        : "=r"(a) : "l"(p));
    return a;
}
__device__ __forceinline__ uint32_t packh(float v0, float v1) {
    uint32_t r;
    asm("cvt.rn.f16x2.f32 %0, %1, %2;" : "=r"(r) : "f"(v1), "f"(v0));
    return r;
}
__device__ __forceinline__ void mma16(float* c, const uint32_t* a,
                                      uint32_t b0, uint32_t b1) {
    asm volatile(
        "mma.sync.aligned.m16n8k16.row.col.f32.f16.f16.f32 "
        "{%0,%1,%2,%3}, {%4,%5,%6,%7}, {%8,%9}, {%0,%1,%2,%3};"
        : "+f"(c[0]), "+f"(c[1]), "+f"(c[2]), "+f"(c[3])
        : "r"(a[0]), "r"(a[1]), "r"(a[2]), "r"(a[3]), "r"(b0), "r"(b1));
}
__device__ __forceinline__ void mma8(float* c, uint32_t a0, uint32_t a1,
                                     uint32_t b0) {
    asm volatile(
        "mma.sync.aligned.m16n8k8.row.col.f32.f16.f16.f32 "
        "{%0,%1,%2,%3}, {%4,%5}, {%6}, {%0,%1,%2,%3};"
        : "+f"(c[0]), "+f"(c[1]), "+f"(c[2]), "+f"(c[3])
        : "r"(a0), "r"(a1), "r"(b0));
}
__device__ __forceinline__ void ldm4(uint32_t* r, uint32_t a) {
    asm volatile("ldmatrix.sync.aligned.m8n8.x4.shared.b16 {%0,%1,%2,%3}, [%4];"
                 : "=r"(r[0]), "=r"(r[1]), "=r"(r[2]), "=r"(r[3]) : "r"(a));
}
__device__ __forceinline__ void ldm2(uint32_t* r, uint32_t a) {
    asm volatile("ldmatrix.sync.aligned.m8n8.x2.shared.b16 {%0,%1}, [%2];"
                 : "=r"(r[0]), "=r"(r[1]) : "r"(a));
}
__device__ __forceinline__ void ldm1(uint32_t* r, uint32_t a) {
    asm volatile("ldmatrix.sync.aligned.m8n8.x1.shared.b16 {%0}, [%1];"
                 : "=r"(r[0]) : "r"(a));
}

// per-warp tile compute with software-pipelined fragment loads.
template<int NTQ>
__device__ __forceinline__ void compute_tile(
    uint32_t aA0, uint32_t aA1, uint32_t aB0, uint32_t aB1, uint32_t aB4,
    uint32_t aAt, uint32_t aBt, uint32_t aBt4,
    const float* __restrict__ bias, const float* __restrict__ csm,
    float* __restrict__ a1, float* __restrict__ chiout,
    int m0, int rv, int band, int q, int g, int t4)
{
    float acc[2][NTQ][4];
#pragma unroll
    for (int mt = 0; mt < 2; mt++)
#pragma unroll
        for (int nt = 0; nt < NTQ; nt++) {
            int col = (nt < 4) ? (q * 32 + nt * 8 + t4 * 2) : (128 + t4 * 2);
            float b0 = bias[col], b1 = bias[col + 1];
            acc[mt][nt][0] = b0; acc[mt][nt][1] = b1;
            acc[mt][nt][2] = b0; acc[mt][nt][3] = b1;
        }

    // double-buffered fragments: prefetch ks+1 before MMAs of ks
    uint32_t Af[2][2][4];
    uint32_t Bf[2][10];
    ldm4(Af[0][0], aA0);
    ldm4(Af[0][1], aA1);
    ldm4(&Bf[0][0], aB0);
    ldm4(&Bf[0][4], aB1);
    if (NTQ == 5) ldm2(&Bf[0][8], aB4);

#pragma unroll
    for (int ks = 0; ks < 8; ks++) {
        const int cur = ks & 1, nxt = cur ^ 1;
        if (ks < 7) {
            ldm4(Af[nxt][0], aA0 + (ks + 1) * 32);
            ldm4(Af[nxt][1], aA1 + (ks + 1) * 32);
            ldm4(&Bf[nxt][0], aB0 + (ks + 1) * 32);
            ldm4(&Bf[nxt][4], aB1 + (ks + 1) * 32);
            if (NTQ == 5) ldm2(&Bf[nxt][8], aB4 + (ks + 1) * 32);
        }
        const uint32_t* B = Bf[cur];
        mma16(acc[0][0], Af[cur][0], B[0], B[1]);
        mma16(acc[1][0], Af[cur][1], B[0], B[1]);
        mma16(acc[0][1], Af[cur][0], B[2], B[3]);
        mma16(acc[1][1], Af[cur][1], B[2], B[3]);
        mma16(acc[0][2], Af[cur][0], B[4], B[5]);
        mma16(acc[1][2], Af[cur][1], B[4], B[5]);
        mma16(acc[0][3], Af[cur][0], B[6], B[7]);
        mma16(acc[1][3], Af[cur][1], B[6], B[7]);
        if (NTQ == 5) {
            mma16(acc[0][4], Af[cur][0], B[8], B[9]);
            mma16(acc[1][4], Af[cur][1], B[8], B[9]);
        }
    }
    // tail k8 (d_chi k-rows 128..135)
    {
        uint32_t TA[4], TB[4], TB4[1];
        ldm4(TA, aAt);
        ldm4(TB, aBt);
        if (NTQ == 5) ldm1(TB4, aBt4);
#pragma unroll
        for (int nt = 0; nt < 4; nt++) {
            mma8(acc[0][nt], TA[0], TA[1], TB[nt]);
            mma8(acc[1][nt], TA[2], TA[3], TB[nt]);
        }
        if (NTQ == 5) {
            mma8(acc[0][4], TA[0], TA[1], TB4[0]);
            mma8(acc[1][4], TA[2], TA[3], TB4[0]);
        }
    }
    // epilogue: a1
    {
        float* ab = a1 + (size_t)m0 * F_;
#pragma unroll
        for (int mt = 0; mt < 2; mt++) {
            int r0 = band * 32 + mt * 16 + g;
            int r1 = r0 + 8;
            bool v0 = (r0 < rv), v1 = (r1 < rv);
#pragma unroll
            for (int nt = 0; nt < 4; nt++) {
                int col = q * 32 + nt * 8 + t4 * 2;
                if (v0) *(float2*)&ab[(size_t)r0 * F_ + col] =
                            make_float2(acc[mt][nt][0], acc[mt][nt][1]);
                if (v1) *(float2*)&ab[(size_t)r1 * F_ + col] =
                            make_float2(acc[mt][nt][2], acc[mt][nt][3]);
            }
        }
    }
    // chi_out from cols 128..131 (only the NTQ==5 quarter)
    if (NTQ == 5) {
#pragma unroll
        for (int mt = 0; mt < 2; mt++) {
            float c0 = acc[mt][4][0], c1 = acc[mt][4][1];
            float c2 = acc[mt][4][2], c3 = acc[mt][4][3];
            float o0 = __shfl_xor_sync(0xFFFFFFFFu, c0, 1);
            float o2 = __shfl_xor_sync(0xFFFFFFFFu, c2, 1);
            int rr0 = band * 32 + mt * 16 + g;
            int rr[2] = {rr0, rr0 + 8};
            if (t4 == 0) {
                float b0r[2] = {c0, c2}, b1r[2] = {c1, c3}, b2r[2] = {o0, o2};
#pragma unroll
                for (int h = 0; h < 2; h++) {
                    if (rr[h] < rv) {
                        const float* cr = &csm[rr[h] * CSTR_W];
                        float4 ca = *(const float4*)&cr[0];
                        float4 cb = *(const float4*)&cr[4];
                        float4 u, w;
                        u.x = b0r[h] * ca.x; u.y = b1r[h] * ca.y;
                        u.z = b1r[h] * ca.z; u.w = b1r[h] * ca.w;
                        w.x = b2r[h] * cb.x; w.y = b2r[h] * cb.y;
                        w.z = b2r[h] * cb.z; w.w = b2r[h] * cb.w;
                        float* op = &chiout[(size_t)(m0 + rr[h]) * 16];
                        *(float4*)&op[0] = u;
                        *(float4*)&op[4] = w;
                    }
                }
            } else if (t4 == 1) {
                float b2r[2] = {c0, c2}, b3r[2] = {c1, c3};
#pragma unroll
                for (int h = 0; h < 2; h++) {
                    if (rr[h] < rv) {
                        const float* cr = &csm[rr[h] * CSTR_W];
                        float4 ca = *(const float4*)&cr[8];
                        float4 cb = *(const float4*)&cr[12];
                        float4 u, w;
                        u.x = b2r[h] * ca.x; u.y = b3r[h] * ca.y;
                        u.z = b3r[h] * ca.z; u.w = b3r[h] * ca.w;
                        w.x = b3r[h] * cb.x; w.y = b3r[h] * cb.y;
                        w.z = b3r[h] * cb.z; w.w = b3r[h] * cb.w;
                        float* op = &chiout[(size_t)(m0 + rr[h]) * 16];
                        *(float4*)&op[8]  = u;
                        *(float4*)&op[12] = w;
                    }
                }
            }
        }
    }
}

// store a fetched tile (registers) into the A/chi stage
__device__ __forceinline__ void store_tile(
    char* __restrict__ sm, float* __restrict__ csm,
    const float4* __restrict__ xr, float4 cv, int tid)
{
    char* ab = sm + OFF_A;
#pragma unroll
    for (int j = 0; j < 8; j++) {
        int e = tid + j * NTHR;
        int row = e >> 5, c4 = e & 31;
        uint32_t h0 = packh(xr[j].x, xr[j].y);
        uint32_t h1 = packh(xr[j].z, xr[j].w);
        *(uint2*)(ab + row * ASTR_B + c4 * 8) = make_uint2(h0, h1);
    }
    int rowc = tid >> 2, seg = tid & 3;
    *(float4*)&csm[rowc * CSTR_W + seg * 4] = cv;
    float xx = cv.x * cv.x, yy = cv.y * cv.y, zz = cv.z * cv.z, ww = cv.w * cv.w;
    float av, bv;
    if (seg == 0)      { av = xx;                bv = yy + zz + ww; }
    else if (seg == 1) { av = xx + yy + zz + ww; bv = 0.f; }
    else if (seg == 2) { av = xx;                bv = yy + zz + ww; }
    else               { av = 0.f;               bv = xx + yy + zz + ww; }
    float a1v = __shfl_xor_sync(0xFFFFFFFFu, av, 1);
    float a2v = __shfl_xor_sync(0xFFFFFFFFu, av, 2);
    float b2v = __shfl_xor_sync(0xFFFFFFFFu, bv, 2);
    float b3v = __shfl_xor_sync(0xFFFFFFFFu, bv, 3);
    if (seg == 0) {
        uint32_t h0 = packh(av, bv);
        uint32_t h1 = packh(a1v + a2v, b2v + b3v);
        *(uint4*)(ab + rowc * ASTR_B + 256) = make_uint4(h0, h1, 0u, 0u);
    }
}

__device__ __forceinline__ void fetch_tile(
    const float* __restrict__ x, const float* __restrict__ chi,
    float4* __restrict__ xr, float4& cv, int m0, int rv, int tid)
{
#pragma unroll
    for (int j = 0; j < 8; j++) {
        int e = tid + j * NTHR;
        int row = e >> 5, c4 = e & 31;
        xr[j] = make_float4(0.f, 0.f, 0.f, 0.f);
        if (row < rv)
            xr[j] = *(const float4*)(x + (size_t)(m0 + row) * F_ + c4 * 4);
    }
    int rowc = tid >> 2, seg = tid & 3;
    cv = make_float4(0.f, 0.f, 0.f, 0.f);
    if (rowc < rv)
        cv = *(const float4*)(chi + (size_t)(m0 + rowc) * 16 + seg * 4);
}

__global__ __launch_bounds__(NTHR, 1)
void ib_mma_kernel(const float* __restrict__ x, const float* __restrict__ chi,
                   const float* __restrict__ W, const float* __restrict__ b,
                   float* __restrict__ a1, float* __restrict__ chiout, int n)
{
    extern __shared__ char sm[];
    const uint32_t smb = s2u(sm);
    float* csm  = (float*)(sm + OFF_CHI);
    float* bias = (float*)(sm + OFF_BIAS);

    const int tid  = threadIdx.x;
    const int wid  = tid >> 5;
    const int lane = tid & 31;
    const int g    = lane >> 2;
    const int t4   = lane & 3;
    const int band = wid & 3;
    const int q    = wid >> 2;
    const int m    = lane >> 3;
    const int rin  = lane & 7;

    // lane-constant ldmatrix base addresses
    const uint32_t aA0 = smb + OFF_A
        + (uint32_t)(band * 32 + (m & 1) * 8 + rin) * ASTR_B + (uint32_t)(m >> 1) * 16u;
    const uint32_t aA1 = aA0 + 16u * ASTR_B;
    const uint32_t aB0 = smb + OFF_BT
        + (uint32_t)(q * 32 + (m >> 1) * 8 + rin) * BSTR_B + (uint32_t)(m & 1) * 16u;
    const uint32_t aB1 = aB0 + 16u * BSTR_B;
    const uint32_t aB4 = smb + OFF_BT
        + (uint32_t)(q * 32 + 32 + rin) * BSTR_B + (uint32_t)(m & 1) * 16u;
    const uint32_t aAt = smb + OFF_A
        + (uint32_t)(band * 32 + (m >> 1) * 16 + (m & 1) * 8 + rin) * ASTR_B + 256u;
    const uint32_t aBt = smb + OFF_BT
        + (uint32_t)(q * 32 + m * 8 + rin) * BSTR_B + 256u;
    const uint32_t aBt4 = smb + OFF_BT
        + (uint32_t)(q * 32 + 32 + rin) * BSTR_B + 256u;

    const int ntiles = (n + MT_ - 1) / MT_;
    int t = blockIdx.x;

    float4 xr[8];
    float4 cv;

    // prologue: LDG tile0
    {
        int m0 = t * MT_;
        int rv = (n - m0 < MT_) ? (n - m0) : MT_;
        fetch_tile(x, chi, xr, cv, m0, rv, tid);
    }

    // one-time: W -> Bt (f16 [n][k]), bias
    for (int e = tid; e < 136 * 68; e += NTHR) {
        int col = e / 68, kp = e - col * 68;
        int k0 = 2 * kp, k1 = k0 + 1;
        float w0 = (k0 < NE_ && col < NE_) ? W[k0 * NE_ + col] : 0.f;
        float w1 = (k1 < NE_ && col < NE_) ? W[k1 * NE_ + col] : 0.f;
        *(uint32_t*)(sm + OFF_BT + col * BSTR_B + kp * 4) = packh(w0, w1);
    }
    if (tid < 136) bias[tid] = (tid < NE_) ? b[tid] : 0.f;

    // prologue STS of tile0
    store_tile(sm, csm, xr, cv, tid);
    __syncthreads();

    // persistent tile loop (R6 structure: full prefetch at loop top)
    for (; t < ntiles; t += gridDim.x) {
        const int m0 = t * MT_;
        const int rv = (n - m0 < MT_) ? (n - m0) : MT_;
        const int tn = t + gridDim.x;
        const bool more = (tn < ntiles);

        if (more) {
            int m0n = tn * MT_;
            int rvn = (n - m0n < MT_) ? (n - m0n) : MT_;
            fetch_tile(x, chi, xr, cv, m0n, rvn, tid);
        }

        if (q == 3)
            compute_tile<5>(aA0, aA1, aB0, aB1, aB4, aAt, aBt, aBt4,
                            bias, csm, a1, chiout, m0, rv, band, q, g, t4);
        else
            compute_tile<4>(aA0, aA1, aB0, aB1, aB4, aAt, aBt, aBt4,
                            bias, csm, a1, chiout, m0, rv, band, q, g, t4);

        __syncthreads();

        if (more) store_tile(sm, csm, xr, cv, tid);

        __syncthreads();
    }
}

extern "C" void kernel_launch(void* const* d_in, const int* in_sizes, int n_in,
                              void* d_out, int out_size) {
    const float* x   = (const float*)d_in[0];
    const float* chi = (const float*)d_in[1];
    // d_in[2] = point_mask (all ones; unused by the math)
    const float* W   = (const float*)d_in[3];
    const float* b   = (const float*)d_in[4];

    const int n = in_sizes[0] / F_;
    float* out    = (float*)d_out;
    float* a1     = out;
    float* chiout = out + (size_t)n * F_;

    cudaFuncSetAttribute(ib_mma_kernel,
                         cudaFuncAttributeMaxDynamicSharedMemorySize, SMEM_REQ);
    int ntiles = (n + MT_ - 1) / MT_;
    int grid = ntiles < 152 ? ntiles : 152;
    ib_mma_kernel<<<grid, NTHR, SMEM_REQ>>>(x, chi, W, b, a1, chiout, n);
}